// round 1
// baseline (speedup 1.0000x reference)
#include <cuda_runtime.h>

#define FD 128          // feature dim D
#define FH 256          // FFN hidden

// ---------------- scratch (device globals; no allocation allowed) -------------
__device__ float g_tmp_u[50000 * FD];    // feat_user @ W_u2i
__device__ float g_tmp_i[50000 * FD];    // feat_item @ W_i2u
__device__ float g_h[100000 * FD];       // h_user rows [0,Mu), h_item rows [Mu,Mu+Mi)
__device__ float g_z[100000 * FH];       // FFN hidden

// ---------------- SGEMM: C[M,N] = A[M,K] @ B[K,N] (+bias) (+relu) -------------
// BM=64, BN=64, BK=16, 256 threads, 4x4 micro-tile per thread.
template<bool RELU>
__global__ void __launch_bounds__(256)
sgemm_kernel(const float* __restrict__ A, const float* __restrict__ B,
             const float* __restrict__ bias, float* __restrict__ C,
             int M, int N, int K)
{
    __shared__ float As[16][65];   // padded to dodge bank conflicts
    __shared__ float Bs[16][64];

    const int tid = threadIdx.x;
    const int tx  = tid & 15;      // n-direction (4 cols each)
    const int ty  = tid >> 4;      // m-direction (4 rows each)
    const int rowBase = blockIdx.x * 64;
    const int colBase = blockIdx.y * 64;

    float acc[4][4] = {};

    for (int k0 = 0; k0 < K; k0 += 16) {
        // A tile 64x16 -> As[k][m] (transposed). k = tid&15, m = tid>>4 (+16*p).
        {
            const int k  = tid & 15;
            const int m0 = tid >> 4;
            #pragma unroll
            for (int p = 0; p < 4; p++) {
                int m = m0 + p * 16;
                int r = rowBase + m;
                As[k][m] = (r < M) ? A[(size_t)r * K + (k0 + k)] : 0.0f;
            }
        }
        // B tile 16x64 via float4. k = tid>>4, n4 = tid&15. (K,N always multiples)
        {
            const int k  = tid >> 4;
            const int n4 = tid & 15;
            float4 v = *(const float4*)&B[(size_t)(k0 + k) * N + colBase + n4 * 4];
            *(float4*)&Bs[k][n4 * 4] = v;
        }
        __syncthreads();

        #pragma unroll
        for (int kk = 0; kk < 16; kk++) {
            float a0 = As[kk][ty * 4 + 0];
            float a1 = As[kk][ty * 4 + 1];
            float a2 = As[kk][ty * 4 + 2];
            float a3 = As[kk][ty * 4 + 3];
            float4 b = *(const float4*)&Bs[kk][tx * 4];
            acc[0][0] += a0 * b.x; acc[0][1] += a0 * b.y; acc[0][2] += a0 * b.z; acc[0][3] += a0 * b.w;
            acc[1][0] += a1 * b.x; acc[1][1] += a1 * b.y; acc[1][2] += a1 * b.z; acc[1][3] += a1 * b.w;
            acc[2][0] += a2 * b.x; acc[2][1] += a2 * b.y; acc[2][2] += a2 * b.z; acc[2][3] += a2 * b.w;
            acc[3][0] += a3 * b.x; acc[3][1] += a3 * b.y; acc[3][2] += a3 * b.z; acc[3][3] += a3 * b.w;
        }
        __syncthreads();
    }

    float4 bv = make_float4(0.f, 0.f, 0.f, 0.f);
    if (bias) bv = *(const float4*)&bias[colBase + tx * 4];

    #pragma unroll
    for (int i = 0; i < 4; i++) {
        int r = rowBase + ty * 4 + i;
        if (r < M) {
            float4 o;
            o.x = acc[i][0] + bv.x;
            o.y = acc[i][1] + bv.y;
            o.z = acc[i][2] + bv.z;
            o.w = acc[i][3] + bv.w;
            if (RELU) {
                o.x = fmaxf(o.x, 0.f); o.y = fmaxf(o.y, 0.f);
                o.z = fmaxf(o.z, 0.f); o.w = fmaxf(o.w, 0.f);
            }
            *(float4*)&C[(size_t)r * N + colBase + tx * 4] = o;
        }
    }
}

// ---------------- edge scatter: out[dst[e], :] += feat[src[e], :] -------------
// 32 threads per edge, float4 gather + 4 scalar atomicAdds.
__global__ void __launch_bounds__(256)
scatter_add_kernel(const float* __restrict__ feat,
                   const int* __restrict__ src, const int* __restrict__ dst,
                   float* __restrict__ out, int E)
{
    int idx = blockIdx.x * blockDim.x + threadIdx.x;
    int e = idx >> 5;
    if (e >= E) return;
    int c = (idx & 31) * 4;
    int s = src[e];
    int d = dst[e];
    float4 v = *(const float4*)&feat[(size_t)s * FD + c];
    float* o = &out[(size_t)d * FD + c];
    atomicAdd(o + 0, v.x);
    atomicAdd(o + 1, v.y);
    atomicAdd(o + 2, v.z);
    atomicAdd(o + 3, v.w);
}

// ---------------- LN -> ReLU -> +residual, warp per row ----------------------
__global__ void __launch_bounds__(256)
ln_relu_res_kernel(float* __restrict__ h, const float* __restrict__ feat,
                   const float* __restrict__ g, const float* __restrict__ b, int M)
{
    int row  = blockIdx.x * 8 + threadIdx.y;
    if (row >= M) return;
    int lane = threadIdx.x;

    float4 x = *(const float4*)&h[(size_t)row * FD + lane * 4];

    float s = x.x + x.y + x.z + x.w;
    #pragma unroll
    for (int off = 16; off > 0; off >>= 1) s += __shfl_xor_sync(0xffffffffu, s, off);
    float mean = s * (1.0f / FD);

    float dx = x.x - mean, dy = x.y - mean, dz = x.z - mean, dw = x.w - mean;
    float q = dx * dx + dy * dy + dz * dz + dw * dw;
    #pragma unroll
    for (int off = 16; off > 0; off >>= 1) q += __shfl_xor_sync(0xffffffffu, q, off);
    float rstd = rsqrtf(q * (1.0f / FD) + 1e-5f);

    float4 gv = *(const float4*)&g[lane * 4];
    float4 bv = *(const float4*)&b[lane * 4];
    float4 fv = *(const float4*)&feat[(size_t)row * FD + lane * 4];

    float4 o;
    o.x = fmaxf(dx * rstd * gv.x + bv.x, 0.f) + fv.x;
    o.y = fmaxf(dy * rstd * gv.y + bv.y, 0.f) + fv.y;
    o.z = fmaxf(dz * rstd * gv.z + bv.z, 0.f) + fv.z;
    o.w = fmaxf(dw * rstd * gv.w + bv.w, 0.f) + fv.w;
    *(float4*)&h[(size_t)row * FD + lane * 4] = o;
}

// ---------------- launch ------------------------------------------------------
extern "C" void kernel_launch(void* const* d_in, const int* in_sizes, int n_in,
                              void* d_out, int out_size)
{
    const float* feat_user   = (const float*)d_in[0];
    const float* feat_item   = (const float*)d_in[1];
    const float* W_u2i       = (const float*)d_in[2];
    const float* b_u2i       = (const float*)d_in[3];
    const float* W_i2u       = (const float*)d_in[4];
    const float* b_i2u       = (const float*)d_in[5];
    const float* self_w_user = (const float*)d_in[6];
    const float* self_w_item = (const float*)d_in[7];
    const float* ln_g_user   = (const float*)d_in[8];
    const float* ln_b_user   = (const float*)d_in[9];
    const float* ln_g_item   = (const float*)d_in[10];
    const float* ln_b_item   = (const float*)d_in[11];
    const float* ffn_w1      = (const float*)d_in[12];
    const float* ffn_b1      = (const float*)d_in[13];
    const float* ffn_w2      = (const float*)d_in[14];
    const float* ffn_b2      = (const float*)d_in[15];
    const int*   src_u2i     = (const int*)d_in[16];
    const int*   dst_u2i     = (const int*)d_in[17];
    const int*   src_i2u     = (const int*)d_in[18];
    const int*   dst_i2u     = (const int*)d_in[19];

    const int Mu = in_sizes[0] / FD;
    const int Mi = in_sizes[1] / FD;
    const int E1 = in_sizes[16];   // u2i edges
    const int E2 = in_sizes[18];   // i2u edges

    float* out = (float*)d_out;

    void *p_tmp_u, *p_tmp_i, *p_h, *p_z;
    cudaGetSymbolAddress(&p_tmp_u, g_tmp_u);
    cudaGetSymbolAddress(&p_tmp_i, g_tmp_i);
    cudaGetSymbolAddress(&p_h, g_h);
    cudaGetSymbolAddress(&p_z, g_z);
    float* tmp_u = (float*)p_tmp_u;
    float* tmp_i = (float*)p_tmp_i;
    float* h     = (float*)p_h;
    float* z     = (float*)p_z;
    float* h_user = h;
    float* h_item = h + (size_t)Mu * FD;

    dim3 blk(256);

    // 1-2: relation transforms of source features
    sgemm_kernel<false><<<dim3((Mu + 63) / 64, FD / 64), blk>>>(feat_user, W_u2i, nullptr, tmp_u, Mu, FD, FD);
    sgemm_kernel<false><<<dim3((Mi + 63) / 64, FD / 64), blk>>>(feat_item, W_i2u, nullptr, tmp_i, Mi, FD, FD);

    // 3-4: self-loop transforms, initialized with the message bias
    sgemm_kernel<false><<<dim3((Mu + 63) / 64, FD / 64), blk>>>(feat_user, self_w_user, b_i2u, h_user, Mu, FD, FD);
    sgemm_kernel<false><<<dim3((Mi + 63) / 64, FD / 64), blk>>>(feat_item, self_w_item, b_u2i, h_item, Mi, FD, FD);

    // 5-6: edge scatter (segment sums)
    {
        int tot1 = E1 * 32, tot2 = E2 * 32;
        scatter_add_kernel<<<(tot2 + 255) / 256, blk>>>(tmp_i, src_i2u, dst_i2u, h_user, E2);
        scatter_add_kernel<<<(tot1 + 255) / 256, blk>>>(tmp_u, src_u2i, dst_u2i, h_item, E1);
    }

    // 7-8: LayerNorm -> ReLU -> residual (in place on h)
    {
        dim3 lblk(32, 8);
        ln_relu_res_kernel<<<(Mu + 7) / 8, lblk>>>(h_user, feat_user, ln_g_user, ln_b_user, Mu);
        ln_relu_res_kernel<<<(Mi + 7) / 8, lblk>>>(h_item, feat_item, ln_g_item, ln_b_item, Mi);
    }

    // 9-10: shared FFN over concatenated rows; final GEMM writes d_out directly
    const int Mt = Mu + Mi;
    sgemm_kernel<true ><<<dim3((Mt + 63) / 64, FH / 64), blk>>>(h, ffn_w1, ffn_b1, z, Mt, FH, FD);
    sgemm_kernel<false><<<dim3((Mt + 63) / 64, FD / 64), blk>>>(z, ffn_w2, ffn_b2, out, Mt, FD, FH);
}

// round 2
// speedup vs baseline: 1.3990x; 1.3990x over previous
#include <cuda_runtime.h>

#define FD 128          // feature dim D
#define FH 256          // FFN hidden

// ---------------- scratch (device globals; no allocation allowed) -------------
__device__ float g_tmp_u[50000 * FD];    // feat_user @ W_u2i
__device__ float g_tmp_i[50000 * FD];    // feat_item @ W_i2u
__device__ float g_h[100000 * FD];       // h_user rows [0,Mu), h_item rows [Mu,)
__device__ float g_z[100000 * FH];       // FFN hidden

// ---------------- SGEMM: C[M,N] = A[M,K] @ B[K,N] (+bias) (+relu) -------------
// BM=128, BN=128, BK=8, 256 threads, 8x8 micro-tile, double-buffered smem.
template<bool RELU>
__global__ void __launch_bounds__(256)
sgemm128(const float* __restrict__ A, const float* __restrict__ B,
         const float* __restrict__ bias, float* __restrict__ C,
         int M, int N, int K)
{
    __shared__ __align__(16) float As[2][8][132];  // [stage][k][m], padded
    __shared__ __align__(16) float Bs[2][8][128];  // [stage][k][n]

    const int tid = threadIdx.x;
    const int m_idx = tid >> 4;        // 0..15  (rows m_idx*4+i and 64+m_idx*4+i)
    const int n_idx = tid & 15;        // 0..15  (cols n_idx*4.. and 64+n_idx*4..)
    const int rowBase = blockIdx.x * 128;
    const int colBase = blockIdx.y * 128;

    // A tile load map: row ar (0..127), k-offset ac in {0,4}
    const int ar = tid >> 1;
    const int ac = (tid & 1) * 4;
    // B tile load map: k-row br (0..7), col bc
    const int br = tid >> 5;
    const int bc = (tid & 31) * 4;

    const int aRow = rowBase + ar;
    const bool aOk = (aRow < M);
    const float* Aptr = A + (size_t)aRow * K + ac;
    const float* Bptr = B + (size_t)br * N + colBase + bc;

    float acc[8][8] = {};

    float4 aReg, bReg;
    // prologue: load tile 0
    aReg = aOk ? *(const float4*)Aptr : make_float4(0.f, 0.f, 0.f, 0.f);
    bReg = *(const float4*)Bptr;
    As[0][ac + 0][ar] = aReg.x;
    As[0][ac + 1][ar] = aReg.y;
    As[0][ac + 2][ar] = aReg.z;
    As[0][ac + 3][ar] = aReg.w;
    *(float4*)&Bs[0][br][bc] = bReg;
    __syncthreads();

    const int nk = K >> 3;
    int buf = 0;
    for (int kt = 0; kt < nk; kt++) {
        const bool more = (kt + 1 < nk);
        if (more) {
            aReg = aOk ? *(const float4*)(Aptr + (kt + 1) * 8)
                       : make_float4(0.f, 0.f, 0.f, 0.f);
            bReg = *(const float4*)(Bptr + (size_t)(kt + 1) * 8 * N);
        }

        #pragma unroll
        for (int kk = 0; kk < 8; kk++) {
            float4 a0 = *(const float4*)&As[buf][kk][m_idx * 4];
            float4 a1 = *(const float4*)&As[buf][kk][64 + m_idx * 4];
            float4 b0 = *(const float4*)&Bs[buf][kk][n_idx * 4];
            float4 b1 = *(const float4*)&Bs[buf][kk][64 + n_idx * 4];
            float am[8] = {a0.x, a0.y, a0.z, a0.w, a1.x, a1.y, a1.z, a1.w};
            float bn[8] = {b0.x, b0.y, b0.z, b0.w, b1.x, b1.y, b1.z, b1.w};
            #pragma unroll
            for (int i = 0; i < 8; i++)
                #pragma unroll
                for (int j = 0; j < 8; j++)
                    acc[i][j] += am[i] * bn[j];
        }

        if (more) {
            int nb = buf ^ 1;
            As[nb][ac + 0][ar] = aReg.x;
            As[nb][ac + 1][ar] = aReg.y;
            As[nb][ac + 2][ar] = aReg.z;
            As[nb][ac + 3][ar] = aReg.w;
            *(float4*)&Bs[nb][br][bc] = bReg;
            __syncthreads();
            buf = nb;
        }
    }

    // epilogue
    float4 bv0 = make_float4(0.f, 0.f, 0.f, 0.f);
    float4 bv1 = make_float4(0.f, 0.f, 0.f, 0.f);
    if (bias) {
        bv0 = *(const float4*)&bias[colBase + n_idx * 4];
        bv1 = *(const float4*)&bias[colBase + 64 + n_idx * 4];
    }

    #pragma unroll
    for (int half = 0; half < 2; half++) {
        #pragma unroll
        for (int i = 0; i < 4; i++) {
            int r = rowBase + half * 64 + m_idx * 4 + i;
            if (r < M) {
                int ii = half * 4 + i;
                float4 o0, o1;
                o0.x = acc[ii][0] + bv0.x; o0.y = acc[ii][1] + bv0.y;
                o0.z = acc[ii][2] + bv0.z; o0.w = acc[ii][3] + bv0.w;
                o1.x = acc[ii][4] + bv1.x; o1.y = acc[ii][5] + bv1.y;
                o1.z = acc[ii][6] + bv1.z; o1.w = acc[ii][7] + bv1.w;
                if (RELU) {
                    o0.x = fmaxf(o0.x, 0.f); o0.y = fmaxf(o0.y, 0.f);
                    o0.z = fmaxf(o0.z, 0.f); o0.w = fmaxf(o0.w, 0.f);
                    o1.x = fmaxf(o1.x, 0.f); o1.y = fmaxf(o1.y, 0.f);
                    o1.z = fmaxf(o1.z, 0.f); o1.w = fmaxf(o1.w, 0.f);
                }
                *(float4*)&C[(size_t)r * N + colBase + n_idx * 4] = o0;
                *(float4*)&C[(size_t)r * N + colBase + 64 + n_idx * 4] = o1;
            }
        }
    }
}

// ---------------- edge scatter: out[dst[e], :] += feat[src[e], :] -------------
// 32 threads per edge; float4 gather + one vector reduction (red.v4.f32).
__global__ void __launch_bounds__(256)
scatter_add_kernel(const float* __restrict__ feat,
                   const int* __restrict__ src, const int* __restrict__ dst,
                   float* __restrict__ out, int E)
{
    int idx = blockIdx.x * blockDim.x + threadIdx.x;
    int e = idx >> 5;
    if (e >= E) return;
    int c = (idx & 31) * 4;
    int s = __ldg(&src[e]);
    int d = __ldg(&dst[e]);
    float4 v = *(const float4*)&feat[(size_t)s * FD + c];
    float* o = &out[(size_t)d * FD + c];
    asm volatile("red.global.add.v4.f32 [%0], {%1, %2, %3, %4};"
                 :: "l"(o), "f"(v.x), "f"(v.y), "f"(v.z), "f"(v.w)
                 : "memory");
}

// ---------------- LN -> ReLU -> +residual, warp per row ----------------------
__global__ void __launch_bounds__(256)
ln_relu_res_kernel(float* __restrict__ h, const float* __restrict__ feat,
                   const float* __restrict__ g, const float* __restrict__ b, int M)
{
    int row  = blockIdx.x * 8 + threadIdx.y;
    if (row >= M) return;
    int lane = threadIdx.x;

    float4 x = *(const float4*)&h[(size_t)row * FD + lane * 4];

    float s = x.x + x.y + x.z + x.w;
    #pragma unroll
    for (int off = 16; off > 0; off >>= 1) s += __shfl_xor_sync(0xffffffffu, s, off);
    float mean = s * (1.0f / FD);

    float dx = x.x - mean, dy = x.y - mean, dz = x.z - mean, dw = x.w - mean;
    float q = dx * dx + dy * dy + dz * dz + dw * dw;
    #pragma unroll
    for (int off = 16; off > 0; off >>= 1) q += __shfl_xor_sync(0xffffffffu, q, off);
    float rstd = rsqrtf(q * (1.0f / FD) + 1e-5f);

    float4 gv = *(const float4*)&g[lane * 4];
    float4 bv = *(const float4*)&b[lane * 4];
    float4 fv = *(const float4*)&feat[(size_t)row * FD + lane * 4];

    float4 o;
    o.x = fmaxf(dx * rstd * gv.x + bv.x, 0.f) + fv.x;
    o.y = fmaxf(dy * rstd * gv.y + bv.y, 0.f) + fv.y;
    o.z = fmaxf(dz * rstd * gv.z + bv.z, 0.f) + fv.z;
    o.w = fmaxf(dw * rstd * gv.w + bv.w, 0.f) + fv.w;
    *(float4*)&h[(size_t)row * FD + lane * 4] = o;
}

// ---------------- launch ------------------------------------------------------
extern "C" void kernel_launch(void* const* d_in, const int* in_sizes, int n_in,
                              void* d_out, int out_size)
{
    const float* feat_user   = (const float*)d_in[0];
    const float* feat_item   = (const float*)d_in[1];
    const float* W_u2i       = (const float*)d_in[2];
    const float* b_u2i       = (const float*)d_in[3];
    const float* W_i2u       = (const float*)d_in[4];
    const float* b_i2u       = (const float*)d_in[5];
    const float* self_w_user = (const float*)d_in[6];
    const float* self_w_item = (const float*)d_in[7];
    const float* ln_g_user   = (const float*)d_in[8];
    const float* ln_b_user   = (const float*)d_in[9];
    const float* ln_g_item   = (const float*)d_in[10];
    const float* ln_b_item   = (const float*)d_in[11];
    const float* ffn_w1      = (const float*)d_in[12];
    const float* ffn_b1      = (const float*)d_in[13];
    const float* ffn_w2      = (const float*)d_in[14];
    const float* ffn_b2      = (const float*)d_in[15];
    const int*   src_u2i     = (const int*)d_in[16];
    const int*   dst_u2i     = (const int*)d_in[17];
    const int*   src_i2u     = (const int*)d_in[18];
    const int*   dst_i2u     = (const int*)d_in[19];

    const int Mu = in_sizes[0] / FD;
    const int Mi = in_sizes[1] / FD;
    const int E1 = in_sizes[16];   // u2i edges
    const int E2 = in_sizes[18];   // i2u edges

    float* out = (float*)d_out;

    void *p_tmp_u, *p_tmp_i, *p_h, *p_z;
    cudaGetSymbolAddress(&p_tmp_u, g_tmp_u);
    cudaGetSymbolAddress(&p_tmp_i, g_tmp_i);
    cudaGetSymbolAddress(&p_h, g_h);
    cudaGetSymbolAddress(&p_z, g_z);
    float* tmp_u = (float*)p_tmp_u;
    float* tmp_i = (float*)p_tmp_i;
    float* h     = (float*)p_h;
    float* z     = (float*)p_z;
    float* h_user = h;
    float* h_item = h + (size_t)Mu * FD;

    dim3 blk(256);

    // 1-2: relation transforms of source features
    sgemm128<false><<<dim3((Mu + 127) / 128, FD / 128), blk>>>(feat_user, W_u2i, nullptr, tmp_u, Mu, FD, FD);
    sgemm128<false><<<dim3((Mi + 127) / 128, FD / 128), blk>>>(feat_item, W_i2u, nullptr, tmp_i, Mi, FD, FD);

    // 3-4: self-loop transforms, initialized with the message bias
    sgemm128<false><<<dim3((Mu + 127) / 128, FD / 128), blk>>>(feat_user, self_w_user, b_i2u, h_user, Mu, FD, FD);
    sgemm128<false><<<dim3((Mi + 127) / 128, FD / 128), blk>>>(feat_item, self_w_item, b_u2i, h_item, Mi, FD, FD);

    // 5-6: edge scatter (segment sums)
    {
        int tot1 = E1 * 32, tot2 = E2 * 32;
        scatter_add_kernel<<<(tot2 + 255) / 256, blk>>>(tmp_i, src_i2u, dst_i2u, h_user, E2);
        scatter_add_kernel<<<(tot1 + 255) / 256, blk>>>(tmp_u, src_u2i, dst_u2i, h_item, E1);
    }

    // 7-8: LayerNorm -> ReLU -> residual (in place on h)
    {
        dim3 lblk(32, 8);
        ln_relu_res_kernel<<<(Mu + 7) / 8, lblk>>>(h_user, feat_user, ln_g_user, ln_b_user, Mu);
        ln_relu_res_kernel<<<(Mi + 7) / 8, lblk>>>(h_item, feat_item, ln_g_item, ln_b_item, Mi);
    }

    // 9-10: shared FFN over concatenated rows; final GEMM writes d_out directly
    const int Mt = Mu + Mi;
    sgemm128<true ><<<dim3((Mt + 127) / 128, FH / 128), blk>>>(h, ffn_w1, ffn_b1, z, Mt, FH, FD);
    sgemm128<false><<<dim3((Mt + 127) / 128, FD / 128), blk>>>(z, ffn_w2, ffn_b2, out, Mt, FD, FH);
}

// round 5
// speedup vs baseline: 1.9419x; 1.3881x over previous
#include <cuda_runtime.h>
#include <cuda_bf16.h>
#include <cstdint>

#define FD 128
#define FH 256

// ---------------- scratch (device globals; no allocation allowed) -------------
__device__ float g_tmp_u[50000 * FD];   // feat_user @ W_u2i  (f32, scatter src)
__device__ float g_tmp_i[50000 * FD];   // feat_item @ W_i2u
__device__ float g_h[100000 * FD];      // h (f32): scatter dst + LN input
// bf16 hi/lo operand arrays
__device__ __align__(16) __nv_bfloat16 g_fu_h[50000 * FD],  g_fu_l[50000 * FD];
__device__ __align__(16) __nv_bfloat16 g_fi_h[50000 * FD],  g_fi_l[50000 * FD];
__device__ __align__(16) __nv_bfloat16 g_hh[100000 * FD],   g_hl[100000 * FD];
__device__ __align__(16) __nv_bfloat16 g_zh[100000 * FH],   g_zl[100000 * FH];
// transposed/split weights, layout [N][K]
__device__ __align__(16) __nv_bfloat16 g_w_u2i_h[FD * FD],  g_w_u2i_l[FD * FD];
__device__ __align__(16) __nv_bfloat16 g_w_i2u_h[FD * FD],  g_w_i2u_l[FD * FD];
__device__ __align__(16) __nv_bfloat16 g_w_su_h[FD * FD],   g_w_su_l[FD * FD];
__device__ __align__(16) __nv_bfloat16 g_w_si_h[FD * FD],   g_w_si_l[FD * FD];
__device__ __align__(16) __nv_bfloat16 g_w_f1_h[FH * FD],   g_w_f1_l[FH * FD];
__device__ __align__(16) __nv_bfloat16 g_w_f2_h[FD * FH],   g_w_f2_l[FD * FH];

// ---------------- PTX helpers --------------------------------------------------
__device__ __forceinline__ uint32_t smem_to_u32(const void* p) {
    uint32_t a;
    asm("{ .reg .u64 t; cvta.to.shared.u64 t, %1; cvt.u32.u64 %0, t; }"
        : "=r"(a) : "l"(p));
    return a;
}
__device__ __forceinline__ void cp16(uint32_t dst, const void* src, bool p) {
    asm volatile("cp.async.cg.shared.global [%0], [%1], 16, %2;"
                 :: "r"(dst), "l"(src), "r"(p ? 16 : 0) : "memory");
}
#define CP_COMMIT() asm volatile("cp.async.commit_group;" ::: "memory")
#define CP_WAIT1()  asm volatile("cp.async.wait_group 1;" ::: "memory")
#define CP_WAIT0()  asm volatile("cp.async.wait_group 0;" ::: "memory")

__device__ __forceinline__ void ldsm4(uint32_t a, uint32_t& r0, uint32_t& r1,
                                      uint32_t& r2, uint32_t& r3) {
    asm volatile("ldmatrix.sync.aligned.m8n8.x4.shared.b16 {%0,%1,%2,%3}, [%4];"
                 : "=r"(r0), "=r"(r1), "=r"(r2), "=r"(r3) : "r"(a));
}
__device__ __forceinline__ void mma_bf16(float* c, const uint32_t* a,
                                         uint32_t b0, uint32_t b1) {
    asm volatile("mma.sync.aligned.m16n8k16.row.col.f32.bf16.bf16.f32 "
                 "{%0,%1,%2,%3}, {%4,%5,%6,%7}, {%8,%9}, {%0,%1,%2,%3};"
                 : "+f"(c[0]), "+f"(c[1]), "+f"(c[2]), "+f"(c[3])
                 : "r"(a[0]), "r"(a[1]), "r"(a[2]), "r"(a[3]), "r"(b0), "r"(b1));
}

// ---------------- weight transpose + bf16 hi/lo split --------------------------
// W stored [K rows, N cols] row-major; output Bt[n*K+k]
__global__ void wsplit_kernel(const float* __restrict__ W, int K, int N,
                              __nv_bfloat16* __restrict__ H, __nv_bfloat16* __restrict__ L)
{
    int i = blockIdx.x * 256 + threadIdx.x;
    if (i >= K * N) return;
    int n = i / K, k = i - n * K;
    float w = W[(size_t)k * N + n];
    __nv_bfloat16 h = __float2bfloat16(w);
    H[i] = h;
    L[i] = __float2bfloat16(w - __bfloat162float(h));
}

// ---------------- f32 -> bf16 hi/lo split (elementwise, float4) ---------------
__global__ void split_f32_kernel(const float* __restrict__ x,
                                 __nv_bfloat16* __restrict__ H,
                                 __nv_bfloat16* __restrict__ L, int n4)
{
    int i = blockIdx.x * 256 + threadIdx.x;
    if (i >= n4) return;
    float4 v = *(const float4*)(x + (size_t)i * 4);
    __nv_bfloat162 h01 = __float22bfloat162_rn(make_float2(v.x, v.y));
    __nv_bfloat162 h23 = __float22bfloat162_rn(make_float2(v.z, v.w));
    float2 f01 = __bfloat1622float2(h01);
    float2 f23 = __bfloat1622float2(h23);
    __nv_bfloat162 l01 = __float22bfloat162_rn(make_float2(v.x - f01.x, v.y - f01.y));
    __nv_bfloat162 l23 = __float22bfloat162_rn(make_float2(v.z - f23.x, v.w - f23.y));
    uint2 hv = make_uint2(*(uint32_t*)&h01, *(uint32_t*)&h23);
    uint2 lv = make_uint2(*(uint32_t*)&l01, *(uint32_t*)&l23);
    *(uint2*)(H + (size_t)i * 4) = hv;
    *(uint2*)(L + (size_t)i * 4) = lv;
}

// ---------------- tensor-core GEMM (mma.sync bf16 3-term) ----------------------
// C[M, ldC] tile 128x128 = A[M,K](hi/lo) @ B[128,K]^T(hi/lo). grid.y picks the
// (B, bias, out) set. Output: f32 (outF) or relu+bf16-split (outH/outL).
// smem: 2 stages x 64KB: AH(16K) AL(16K) BH(16K) BL(16K); 128B rows, XOR-swizzled.
__global__ void __launch_bounds__(256)
gemm_mma(const __nv_bfloat16* __restrict__ Ah, const __nv_bfloat16* __restrict__ Al,
         const __nv_bfloat16* __restrict__ Bh0, const __nv_bfloat16* __restrict__ Bl0,
         const __nv_bfloat16* __restrict__ Bh1, const __nv_bfloat16* __restrict__ Bl1,
         const float* __restrict__ bias0, const float* __restrict__ bias1,
         float* __restrict__ outF0, float* __restrict__ outF1,
         __nv_bfloat16* __restrict__ outH, __nv_bfloat16* __restrict__ outL,
         int M, int K, int ldC, int colOff1, int relu)
{
    extern __shared__ char smem[];
    const uint32_t smBase = smem_to_u32(smem);
    const int tid = threadIdx.x;
    const int lane = tid & 31, wid = tid >> 5;
    const int j = blockIdx.y;

    const __nv_bfloat16* Bh = j ? Bh1 : Bh0;
    const __nv_bfloat16* Bl = j ? Bl1 : Bl0;
    const float* bias = j ? bias1 : bias0;
    float* outF = j ? outF1 : outF0;
    const int colOff = j ? colOff1 : 0;
    const int rowBase = blockIdx.x * 128;
    const int nc = K >> 6;

    // ---- cp.async issue mapping: thread pair per row, 4x16B segs each --------
    const int ir = tid >> 1;
    const int ikh = tid & 1;
    const bool aOk = (rowBase + ir) < M;
    const size_t aBase = (size_t)(aOk ? rowBase + ir : 0) * K;
    const size_t bBase = (size_t)ir * K;

    auto issue = [&](int c, int s) {
        uint32_t stA = smBase + s * 65536;
        uint32_t stB = stA + 32768;
        #pragma unroll
        for (int i = 0; i < 4; i++) {
            int byteoff = ikh * 64 + i * 16;
            uint32_t doff = (uint32_t)ir * 128 + (uint32_t)(byteoff ^ ((ir & 7) << 4));
            int kOff = c * 64 + (byteoff >> 1);
            cp16(stA + doff,         Ah + aBase + kOff, aOk);
            cp16(stA + 16384 + doff, Al + aBase + kOff, aOk);
            cp16(stB + doff,         Bh + bBase + kOff, true);
            cp16(stB + 16384 + doff, Bl + bBase + kOff, true);
        }
        CP_COMMIT();
    };

    // ---- per-lane ldmatrix address components --------------------------------
    const int m0w = (wid & 3) * 32;
    const int n0w = (wid >> 2) * 64;
    const int rA = lane & 15;
    const uint32_t kxA = (uint32_t)((lane >> 4) << 4);    // 0 or 16 bytes
    const uint32_t aoff = (uint32_t)(m0w + rA) * 128;
    const uint32_t axor = (uint32_t)((rA & 7) << 4);
    const int rB = (lane & 7) + ((lane >> 4) << 3);       // +8 if lane>=16
    const uint32_t kxB = (uint32_t)((lane & 8) << 1);     // 0 or 16 bytes
    const uint32_t bxor = (uint32_t)((rB & 7) << 4);

    float acc[2][8][4];
    #pragma unroll
    for (int a = 0; a < 2; a++)
        #pragma unroll
        for (int b = 0; b < 8; b++)
            #pragma unroll
            for (int c = 0; c < 4; c++) acc[a][b][c] = 0.f;

    issue(0, 0);
    if (nc > 1) issue(1, 1);

    for (int c = 0; c < nc; c++) {
        if (c + 1 < nc) CP_WAIT1(); else CP_WAIT0();
        __syncthreads();

        const int s = c & 1;
        const uint32_t AHs = smBase + s * 65536;
        const uint32_t ALs = AHs + 16384;
        const uint32_t BHs = AHs + 32768;
        const uint32_t BLs = AHs + 49152;

        #pragma unroll
        for (int kk4 = 0; kk4 < 4; kk4++) {
            const uint32_t kb = (uint32_t)kk4 * 32;   // k16 step in bytes
            uint32_t ah[2][4], al[2][4];
            #pragma unroll
            for (int mt = 0; mt < 2; mt++) {
                uint32_t ad = aoff + (uint32_t)mt * 2048 + ((kb + kxA) ^ axor);
                ldsm4(AHs + ad, ah[mt][0], ah[mt][1], ah[mt][2], ah[mt][3]);
                ldsm4(ALs + ad, al[mt][0], al[mt][1], al[mt][2], al[mt][3]);
            }
            #pragma unroll
            for (int ng = 0; ng < 4; ng++) {
                uint32_t bd = (uint32_t)(n0w + ng * 16 + rB) * 128 + ((kb + kxB) ^ bxor);
                uint32_t bh[4], bl[4];
                ldsm4(BHs + bd, bh[0], bh[1], bh[2], bh[3]);
                ldsm4(BLs + bd, bl[0], bl[1], bl[2], bl[3]);
                #pragma unroll
                for (int mt = 0; mt < 2; mt++) {
                    mma_bf16(acc[mt][ng * 2 + 0], ah[mt], bh[0], bh[1]);
                    mma_bf16(acc[mt][ng * 2 + 0], ah[mt], bl[0], bl[1]);
                    mma_bf16(acc[mt][ng * 2 + 0], al[mt], bh[0], bh[1]);
                    mma_bf16(acc[mt][ng * 2 + 1], ah[mt], bh[2], bh[3]);
                    mma_bf16(acc[mt][ng * 2 + 1], ah[mt], bl[2], bl[3]);
                    mma_bf16(acc[mt][ng * 2 + 1], al[mt], bh[2], bh[3]);
                }
            }
        }
        __syncthreads();
        if (c + 2 < nc) issue(c + 2, s);
    }

    // ---- epilogue ------------------------------------------------------------
    const int g = lane >> 2, tig = lane & 3;
    #pragma unroll
    for (int mt = 0; mt < 2; mt++) {
        const int r0 = rowBase + m0w + mt * 16 + g;
        #pragma unroll
        for (int t = 0; t < 8; t++) {
            const int col = colOff + n0w + t * 8 + tig * 2;
            float b0 = 0.f, b1 = 0.f;
            if (bias) { b0 = __ldg(bias + col); b1 = __ldg(bias + col + 1); }
            float v00 = acc[mt][t][0] + b0, v01 = acc[mt][t][1] + b1;
            float v10 = acc[mt][t][2] + b0, v11 = acc[mt][t][3] + b1;
            if (relu) {
                v00 = fmaxf(v00, 0.f); v01 = fmaxf(v01, 0.f);
                v10 = fmaxf(v10, 0.f); v11 = fmaxf(v11, 0.f);
            }
            if (outF) {
                if (r0 < M)     *(float2*)&outF[(size_t)r0 * ldC + col]       = make_float2(v00, v01);
                if (r0 + 8 < M) *(float2*)&outF[(size_t)(r0 + 8) * ldC + col] = make_float2(v10, v11);
            } else {
                if (r0 < M) {
                    __nv_bfloat162 hv = __float22bfloat162_rn(make_float2(v00, v01));
                    float2 hf = __bfloat1622float2(hv);
                    __nv_bfloat162 lv = __float22bfloat162_rn(make_float2(v00 - hf.x, v01 - hf.y));
                    *(__nv_bfloat162*)&outH[(size_t)r0 * ldC + col] = hv;
                    *(__nv_bfloat162*)&outL[(size_t)r0 * ldC + col] = lv;
                }
                if (r0 + 8 < M) {
                    __nv_bfloat162 hv = __float22bfloat162_rn(make_float2(v10, v11));
                    float2 hf = __bfloat1622float2(hv);
                    __nv_bfloat162 lv = __float22bfloat162_rn(make_float2(v10 - hf.x, v11 - hf.y));
                    *(__nv_bfloat162*)&outH[(size_t)(r0 + 8) * ldC + col] = hv;
                    *(__nv_bfloat162*)&outL[(size_t)(r0 + 8) * ldC + col] = lv;
                }
            }
        }
    }
}

// ---------------- edge scatter ------------------------------------------------
__global__ void __launch_bounds__(256)
scatter_add_kernel(const float* __restrict__ feat,
                   const int* __restrict__ src, const int* __restrict__ dst,
                   float* __restrict__ out, int E)
{
    int idx = blockIdx.x * blockDim.x + threadIdx.x;
    int e = idx >> 5;
    if (e >= E) return;
    int c = (idx & 31) * 4;
    int s = __ldg(&src[e]);
    int d = __ldg(&dst[e]);
    float4 v = *(const float4*)&feat[(size_t)s * FD + c];
    float* o = &out[(size_t)d * FD + c];
    asm volatile("red.global.add.v4.f32 [%0], {%1, %2, %3, %4};"
                 :: "l"(o), "f"(v.x), "f"(v.y), "f"(v.z), "f"(v.w) : "memory");
}

// ---------------- LN -> ReLU -> +residual, output bf16 hi/lo -------------------
__global__ void __launch_bounds__(256)
ln_relu_res_split(const float* __restrict__ h, const float* __restrict__ feat,
                  const float* __restrict__ g, const float* __restrict__ b,
                  __nv_bfloat16* __restrict__ outH, __nv_bfloat16* __restrict__ outL,
                  int M)
{
    int row = blockIdx.x * 8 + threadIdx.y;
    if (row >= M) return;
    int lane = threadIdx.x;

    float4 x = *(const float4*)&h[(size_t)row * FD + lane * 4];
    float s = x.x + x.y + x.z + x.w;
    #pragma unroll
    for (int off = 16; off > 0; off >>= 1) s += __shfl_xor_sync(0xffffffffu, s, off);
    float mean = s * (1.0f / FD);
    float dx = x.x - mean, dy = x.y - mean, dz = x.z - mean, dw = x.w - mean;
    float q = dx * dx + dy * dy + dz * dz + dw * dw;
    #pragma unroll
    for (int off = 16; off > 0; off >>= 1) q += __shfl_xor_sync(0xffffffffu, q, off);
    float rstd = rsqrtf(q * (1.0f / FD) + 1e-5f);

    float4 gv = *(const float4*)&g[lane * 4];
    float4 bv = *(const float4*)&b[lane * 4];
    float4 fv = *(const float4*)&feat[(size_t)row * FD + lane * 4];
    float4 o;
    o.x = fmaxf(dx * rstd * gv.x + bv.x, 0.f) + fv.x;
    o.y = fmaxf(dy * rstd * gv.y + bv.y, 0.f) + fv.y;
    o.z = fmaxf(dz * rstd * gv.z + bv.z, 0.f) + fv.z;
    o.w = fmaxf(dw * rstd * gv.w + bv.w, 0.f) + fv.w;

    __nv_bfloat162 h01 = __float22bfloat162_rn(make_float2(o.x, o.y));
    __nv_bfloat162 h23 = __float22bfloat162_rn(make_float2(o.z, o.w));
    float2 f01 = __bfloat1622float2(h01);
    float2 f23 = __bfloat1622float2(h23);
    __nv_bfloat162 l01 = __float22bfloat162_rn(make_float2(o.x - f01.x, o.y - f01.y));
    __nv_bfloat162 l23 = __float22bfloat162_rn(make_float2(o.z - f23.x, o.w - f23.y));
    uint2 hv = make_uint2(*(uint32_t*)&h01, *(uint32_t*)&h23);
    uint2 lv = make_uint2(*(uint32_t*)&l01, *(uint32_t*)&l23);
    *(uint2*)&outH[(size_t)row * FD + lane * 4] = hv;
    *(uint2*)&outL[(size_t)row * FD + lane * 4] = lv;
}

// ---------------- launch ------------------------------------------------------
extern "C" void kernel_launch(void* const* d_in, const int* in_sizes, int n_in,
                              void* d_out, int out_size)
{
    const float* feat_user   = (const float*)d_in[0];
    const float* feat_item   = (const float*)d_in[1];
    const float* W_u2i       = (const float*)d_in[2];
    const float* b_u2i       = (const float*)d_in[3];
    const float* W_i2u       = (const float*)d_in[4];
    const float* b_i2u       = (const float*)d_in[5];
    const float* self_w_user = (const float*)d_in[6];
    const float* self_w_item = (const float*)d_in[7];
    const float* ln_g_user   = (const float*)d_in[8];
    const float* ln_b_user   = (const float*)d_in[9];
    const float* ln_g_item   = (const float*)d_in[10];
    const float* ln_b_item   = (const float*)d_in[11];
    const float* ffn_w1      = (const float*)d_in[12];
    const float* ffn_b1      = (const float*)d_in[13];
    const float* ffn_w2      = (const float*)d_in[14];
    const float* ffn_b2      = (const float*)d_in[15];
    const int*   src_u2i     = (const int*)d_in[16];
    const int*   dst_u2i     = (const int*)d_in[17];
    const int*   src_i2u     = (const int*)d_in[18];
    const int*   dst_i2u     = (const int*)d_in[19];

    const int Mu = in_sizes[0] / FD;
    const int Mi = in_sizes[1] / FD;
    const int E1 = in_sizes[16];
    const int E2 = in_sizes[18];
    float* out = (float*)d_out;

    auto sym = [](const void* s) { void* p; cudaGetSymbolAddress(&p, s); return p; };
    float* tmp_u = (float*)sym(g_tmp_u);
    float* tmp_i = (float*)sym(g_tmp_i);
    float* h     = (float*)sym(g_h);
    __nv_bfloat16* fu_h = (__nv_bfloat16*)sym(g_fu_h);
    __nv_bfloat16* fu_l = (__nv_bfloat16*)sym(g_fu_l);
    __nv_bfloat16* fi_h = (__nv_bfloat16*)sym(g_fi_h);
    __nv_bfloat16* fi_l = (__nv_bfloat16*)sym(g_fi_l);
    __nv_bfloat16* hh   = (__nv_bfloat16*)sym(g_hh);
    __nv_bfloat16* hl   = (__nv_bfloat16*)sym(g_hl);
    __nv_bfloat16* zh   = (__nv_bfloat16*)sym(g_zh);
    __nv_bfloat16* zl   = (__nv_bfloat16*)sym(g_zl);
    __nv_bfloat16* w_u2i_h = (__nv_bfloat16*)sym(g_w_u2i_h);
    __nv_bfloat16* w_u2i_l = (__nv_bfloat16*)sym(g_w_u2i_l);
    __nv_bfloat16* w_i2u_h = (__nv_bfloat16*)sym(g_w_i2u_h);
    __nv_bfloat16* w_i2u_l = (__nv_bfloat16*)sym(g_w_i2u_l);
    __nv_bfloat16* w_su_h  = (__nv_bfloat16*)sym(g_w_su_h);
    __nv_bfloat16* w_su_l  = (__nv_bfloat16*)sym(g_w_su_l);
    __nv_bfloat16* w_si_h  = (__nv_bfloat16*)sym(g_w_si_h);
    __nv_bfloat16* w_si_l  = (__nv_bfloat16*)sym(g_w_si_l);
    __nv_bfloat16* w_f1_h  = (__nv_bfloat16*)sym(g_w_f1_h);
    __nv_bfloat16* w_f1_l  = (__nv_bfloat16*)sym(g_w_f1_l);
    __nv_bfloat16* w_f2_h  = (__nv_bfloat16*)sym(g_w_f2_h);
    __nv_bfloat16* w_f2_l  = (__nv_bfloat16*)sym(g_w_f2_l);

    float* h_user = h;
    float* h_item = h + (size_t)Mu * FD;

    const int SMEM = 131072;
    cudaFuncSetAttribute(gemm_mma, cudaFuncAttributeMaxDynamicSharedMemorySize, SMEM);

    // 0: weight transpose/split + feature split
    wsplit_kernel<<<(FD*FD + 255)/256, 256>>>(W_u2i,       FD, FD, w_u2i_h, w_u2i_l);
    wsplit_kernel<<<(FD*FD + 255)/256, 256>>>(W_i2u,       FD, FD, w_i2u_h, w_i2u_l);
    wsplit_kernel<<<(FD*FD + 255)/256, 256>>>(self_w_user, FD, FD, w_su_h,  w_su_l);
    wsplit_kernel<<<(FD*FD + 255)/256, 256>>>(self_w_item, FD, FD, w_si_h,  w_si_l);
    wsplit_kernel<<<(FD*FH + 255)/256, 256>>>(ffn_w1,      FD, FH, w_f1_h,  w_f1_l);
    wsplit_kernel<<<(FH*FD + 255)/256, 256>>>(ffn_w2,      FH, FD, w_f2_h,  w_f2_l);
    split_f32_kernel<<<(Mu*FD/4 + 255)/256, 256>>>(feat_user, fu_h, fu_l, Mu*FD/4);
    split_f32_kernel<<<(Mi*FD/4 + 255)/256, 256>>>(feat_item, fi_h, fi_l, Mi*FD/4);

    // 1: user feats x {W_u2i -> tmp_u | self_w_user + b_i2u -> h_user}
    gemm_mma<<<dim3((Mu + 127)/128, 2), 256, SMEM>>>(
        fu_h, fu_l, w_u2i_h, w_u2i_l, w_su_h, w_su_l,
        nullptr, b_i2u, tmp_u, h_user, nullptr, nullptr, Mu, FD, FD, 0, 0);
    // 2: item feats x {W_i2u -> tmp_i | self_w_item + b_u2i -> h_item}
    gemm_mma<<<dim3((Mi + 127)/128, 2), 256, SMEM>>>(
        fi_h, fi_l, w_i2u_h, w_i2u_l, w_si_h, w_si_l,
        nullptr, b_u2i, tmp_i, h_item, nullptr, nullptr, Mi, FD, FD, 0, 0);

    // 3: edge scatter (segment sums)
    scatter_add_kernel<<<(E2*32 + 255)/256, 256>>>(tmp_i, src_i2u, dst_i2u, h_user, E2);
    scatter_add_kernel<<<(E1*32 + 255)/256, 256>>>(tmp_u, src_u2i, dst_u2i, h_item, E1);

    // 4: LN -> ReLU -> residual, emit bf16 hi/lo
    {
        dim3 lblk(32, 8);
        ln_relu_res_split<<<(Mu + 7)/8, lblk>>>(h_user, feat_user, ln_g_user, ln_b_user,
                                                hh, hl, Mu);
        ln_relu_res_split<<<(Mi + 7)/8, lblk>>>(h_item, feat_item, ln_g_item, ln_b_item,
                                                hh + (size_t)Mu * FD, hl + (size_t)Mu * FD, Mi);
    }

    // 5: FFN1: [Mt,128] @ w1 -> relu -> bf16 split z (N=256 via grid.y halves)
    const int Mt = Mu + Mi;
    gemm_mma<<<dim3((Mt + 127)/128, 2), 256, SMEM>>>(
        hh, hl, w_f1_h, w_f1_l, w_f1_h + 128*FD, w_f1_l + 128*FD,
        ffn_b1, ffn_b1, nullptr, nullptr, zh, zl, Mt, FD, FH, 128, 1);
    // 6: FFN2: [Mt,256] @ w2 + b2 -> out (f32)
    gemm_mma<<<dim3((Mt + 127)/128, 1), 256, SMEM>>>(
        zh, zl, w_f2_h, w_f2_l, w_f2_h, w_f2_l,
        ffn_b2, ffn_b2, out, out, nullptr, nullptr, Mt, FH, FD, 0, 0);
}

// round 6
// speedup vs baseline: 2.5425x; 1.3092x over previous
#include <cuda_runtime.h>
#include <cuda_fp16.h>
#include <cstdint>

#define FD 128
#define FH 256

// ---------------- scratch (device globals; no allocation allowed) -------------
__device__ float g_tmp_u[50000 * FD];   // feat_user @ W_u2i  (f32, scatter src)
__device__ float g_tmp_i[50000 * FD];   // feat_item @ W_i2u
__device__ float g_h[100000 * FD];      // h (f32): scatter dst + LN input
// fp16 hi/lo activation operands
__device__ __align__(16) __half g_fu_h[50000 * FD],  g_fu_l[50000 * FD];
__device__ __align__(16) __half g_fi_h[50000 * FD],  g_fi_l[50000 * FD];
__device__ __align__(16) __half g_hh[100000 * FD],   g_hl[100000 * FD];
__device__ __align__(16) __half g_zh[100000 * FH],   g_zl[100000 * FH];
// transposed weights, fp16 (hi only — B needs no lo), layout [N][K]
__device__ __align__(16) __half g_w_u2i[FD * FD];
__device__ __align__(16) __half g_w_i2u[FD * FD];
__device__ __align__(16) __half g_w_su[FD * FD];
__device__ __align__(16) __half g_w_si[FD * FD];
__device__ __align__(16) __half g_w_f1[FH * FD];
__device__ __align__(16) __half g_w_f2[FD * FH];

// ---------------- PTX helpers --------------------------------------------------
__device__ __forceinline__ uint32_t smem_to_u32(const void* p) {
    uint32_t a;
    asm("{ .reg .u64 t; cvta.to.shared.u64 t, %1; cvt.u32.u64 %0, t; }"
        : "=r"(a) : "l"(p));
    return a;
}
__device__ __forceinline__ void cp16(uint32_t dst, const void* src, bool p) {
    asm volatile("cp.async.cg.shared.global [%0], [%1], 16, %2;"
                 :: "r"(dst), "l"(src), "r"(p ? 16 : 0) : "memory");
}
#define CP_COMMIT() asm volatile("cp.async.commit_group;" ::: "memory")
#define CP_WAIT1()  asm volatile("cp.async.wait_group 1;" ::: "memory")
#define CP_WAIT0()  asm volatile("cp.async.wait_group 0;" ::: "memory")

__device__ __forceinline__ void ldsm4(uint32_t a, uint32_t& r0, uint32_t& r1,
                                      uint32_t& r2, uint32_t& r3) {
    asm volatile("ldmatrix.sync.aligned.m8n8.x4.shared.b16 {%0,%1,%2,%3}, [%4];"
                 : "=r"(r0), "=r"(r1), "=r"(r2), "=r"(r3) : "r"(a));
}
__device__ __forceinline__ void mma_fp16(float* c, const uint32_t* a,
                                         uint32_t b0, uint32_t b1) {
    asm volatile("mma.sync.aligned.m16n8k16.row.col.f32.f16.f16.f32 "
                 "{%0,%1,%2,%3}, {%4,%5,%6,%7}, {%8,%9}, {%0,%1,%2,%3};"
                 : "+f"(c[0]), "+f"(c[1]), "+f"(c[2]), "+f"(c[3])
                 : "r"(a[0]), "r"(a[1]), "r"(a[2]), "r"(a[3]), "r"(b0), "r"(b1));
}

// ---------------- all-weights transpose + fp16 round (one launch) --------------
// W stored [K rows, N cols] row-major; output Wt[n*K+k] fp16.
__global__ void __launch_bounds__(256)
wtrans_all(const float* __restrict__ W0, const float* __restrict__ W1,
           const float* __restrict__ W2, const float* __restrict__ W3,
           const float* __restrict__ W4, const float* __restrict__ W5,
           __half* __restrict__ H0, __half* __restrict__ H1,
           __half* __restrict__ H2, __half* __restrict__ H3,
           __half* __restrict__ H4, __half* __restrict__ H5)
{
    const float* W; __half* H; int K, N;
    switch (blockIdx.y) {
        case 0:  W = W0; H = H0; K = FD; N = FD; break;
        case 1:  W = W1; H = H1; K = FD; N = FD; break;
        case 2:  W = W2; H = H2; K = FD; N = FD; break;
        case 3:  W = W3; H = H3; K = FD; N = FD; break;
        case 4:  W = W4; H = H4; K = FD; N = FH; break;
        default: W = W5; H = H5; K = FH; N = FD; break;
    }
    int i = blockIdx.x * 256 + threadIdx.x;
    if (i >= K * N) return;
    int n = i / K, k = i - n * K;
    H[i] = __float2half_rn(W[(size_t)k * N + n]);
}

// ---------------- feature f32 -> fp16 hi/lo split (both node types, 1 launch) --
__global__ void __launch_bounds__(256)
split_feat(const float* __restrict__ fu, const float* __restrict__ fi,
           __half* __restrict__ fuh, __half* __restrict__ ful,
           __half* __restrict__ fih, __half* __restrict__ fil,
           int n4u, int n4i)
{
    const int y = blockIdx.y;
    const float* x = y ? fi : fu;
    __half* H = y ? fih : fuh;
    __half* L = y ? fil : ful;
    const int n4 = y ? n4i : n4u;
    int i = blockIdx.x * 256 + threadIdx.x;
    if (i >= n4) return;
    float4 v = *(const float4*)(x + (size_t)i * 4);
    __half2 h01 = __float22half2_rn(make_float2(v.x, v.y));
    __half2 h23 = __float22half2_rn(make_float2(v.z, v.w));
    float2 f01 = __half22float2(h01);
    float2 f23 = __half22float2(h23);
    __half2 l01 = __float22half2_rn(make_float2(v.x - f01.x, v.y - f01.y));
    __half2 l23 = __float22half2_rn(make_float2(v.z - f23.x, v.w - f23.y));
    uint2 hv = make_uint2(*(uint32_t*)&h01, *(uint32_t*)&h23);
    uint2 lv = make_uint2(*(uint32_t*)&l01, *(uint32_t*)&l23);
    *(uint2*)(H + (size_t)i * 4) = hv;
    *(uint2*)(L + (size_t)i * 4) = lv;
}

// ---------------- tensor-core GEMM (mma.sync fp16, A=hi+lo, B=hi) --------------
// C[M, ldC] tile 128x128 = (Ah+Al)[M,K] @ B[128,K]^T. grid.y selects (B, bias,
// out) set. Output: f32 (outF) or relu + fp16 hi/lo split (outH/outL).
// smem: 2 stages x 48KB: AH(16K) AL(16K) BH(16K); 128B rows, XOR-swizzled.
__global__ void __launch_bounds__(256)
gemm_mma(const __half* __restrict__ Ah, const __half* __restrict__ Al,
         const __half* __restrict__ Bh0, const __half* __restrict__ Bh1,
         const float* __restrict__ bias0, const float* __restrict__ bias1,
         float* __restrict__ outF0, float* __restrict__ outF1,
         __half* __restrict__ outH, __half* __restrict__ outL,
         int M, int K, int ldC, int colOff1, int relu)
{
    extern __shared__ char smem[];
    const uint32_t smBase = smem_to_u32(smem);
    const int tid = threadIdx.x;
    const int lane = tid & 31, wid = tid >> 5;
    const int j = blockIdx.y;

    const __half* Bh = j ? Bh1 : Bh0;
    const float* bias = j ? bias1 : bias0;
    float* outF = j ? outF1 : outF0;
    const int colOff = j ? colOff1 : 0;
    const int rowBase = blockIdx.x * 128;
    const int nc = K >> 6;

    // cp.async issue mapping: thread pair per row, 4x16B segs each
    const int ir = tid >> 1;
    const int ikh = tid & 1;
    const bool aOk = (rowBase + ir) < M;
    const size_t aBase = (size_t)(aOk ? rowBase + ir : 0) * K;
    const size_t bBase = (size_t)ir * K;

    auto issue = [&](int c, int s) {
        uint32_t st = smBase + s * 49152;
        #pragma unroll
        for (int i = 0; i < 4; i++) {
            int byteoff = ikh * 64 + i * 16;
            uint32_t doff = (uint32_t)ir * 128 + (uint32_t)(byteoff ^ ((ir & 7) << 4));
            int kOff = c * 64 + (byteoff >> 1);
            cp16(st + doff,         Ah + aBase + kOff, aOk);
            cp16(st + 16384 + doff, Al + aBase + kOff, aOk);
            cp16(st + 32768 + doff, Bh + bBase + kOff, true);
        }
        CP_COMMIT();
    };

    // per-lane ldmatrix address components
    const int m0w = (wid & 3) * 32;
    const int n0w = (wid >> 2) * 64;
    const int rA = lane & 15;
    const uint32_t kxA = (uint32_t)((lane >> 4) << 4);
    const uint32_t aoff = (uint32_t)(m0w + rA) * 128;
    const uint32_t axor = (uint32_t)((rA & 7) << 4);
    const int rB = (lane & 7) + ((lane >> 4) << 3);
    const uint32_t kxB = (uint32_t)((lane & 8) << 1);
    const uint32_t bxor = (uint32_t)((rB & 7) << 4);

    float acc[2][8][4];
    #pragma unroll
    for (int a = 0; a < 2; a++)
        #pragma unroll
        for (int b = 0; b < 8; b++)
            #pragma unroll
            for (int c = 0; c < 4; c++) acc[a][b][c] = 0.f;

    issue(0, 0);
    if (nc > 1) issue(1, 1);

    for (int c = 0; c < nc; c++) {
        if (c + 1 < nc) CP_WAIT1(); else CP_WAIT0();
        __syncthreads();

        const int s = c & 1;
        const uint32_t AHs = smBase + s * 49152;
        const uint32_t ALs = AHs + 16384;
        const uint32_t BHs = AHs + 32768;

        #pragma unroll
        for (int kk4 = 0; kk4 < 4; kk4++) {
            const uint32_t kb = (uint32_t)kk4 * 32;
            uint32_t ah[2][4], al[2][4];
            #pragma unroll
            for (int mt = 0; mt < 2; mt++) {
                uint32_t ad = aoff + (uint32_t)mt * 2048 + ((kb + kxA) ^ axor);
                ldsm4(AHs + ad, ah[mt][0], ah[mt][1], ah[mt][2], ah[mt][3]);
                ldsm4(ALs + ad, al[mt][0], al[mt][1], al[mt][2], al[mt][3]);
            }
            #pragma unroll
            for (int ng = 0; ng < 4; ng++) {
                uint32_t bd = (uint32_t)(n0w + ng * 16 + rB) * 128 + ((kb + kxB) ^ bxor);
                uint32_t bh[4];
                ldsm4(BHs + bd, bh[0], bh[1], bh[2], bh[3]);
                #pragma unroll
                for (int mt = 0; mt < 2; mt++) {
                    mma_fp16(acc[mt][ng * 2 + 0], ah[mt], bh[0], bh[1]);
                    mma_fp16(acc[mt][ng * 2 + 0], al[mt], bh[0], bh[1]);
                    mma_fp16(acc[mt][ng * 2 + 1], ah[mt], bh[2], bh[3]);
                    mma_fp16(acc[mt][ng * 2 + 1], al[mt], bh[2], bh[3]);
                }
            }
        }
        __syncthreads();
        if (c + 2 < nc) issue(c + 2, s);
    }

    // epilogue
    const int g = lane >> 2, tig = lane & 3;
    #pragma unroll
    for (int mt = 0; mt < 2; mt++) {
        const int r0 = rowBase + m0w + mt * 16 + g;
        #pragma unroll
        for (int t = 0; t < 8; t++) {
            const int col = colOff + n0w + t * 8 + tig * 2;
            float b0 = 0.f, b1 = 0.f;
            if (bias) { b0 = __ldg(bias + col); b1 = __ldg(bias + col + 1); }
            float v00 = acc[mt][t][0] + b0, v01 = acc[mt][t][1] + b1;
            float v10 = acc[mt][t][2] + b0, v11 = acc[mt][t][3] + b1;
            if (relu) {
                v00 = fmaxf(v00, 0.f); v01 = fmaxf(v01, 0.f);
                v10 = fmaxf(v10, 0.f); v11 = fmaxf(v11, 0.f);
            }
            if (outF) {
                if (r0 < M)     *(float2*)&outF[(size_t)r0 * ldC + col]       = make_float2(v00, v01);
                if (r0 + 8 < M) *(float2*)&outF[(size_t)(r0 + 8) * ldC + col] = make_float2(v10, v11);
            } else {
                if (r0 < M) {
                    __half2 hv = __float22half2_rn(make_float2(v00, v01));
                    float2 hf = __half22float2(hv);
                    __half2 lv = __float22half2_rn(make_float2(v00 - hf.x, v01 - hf.y));
                    *(__half2*)&outH[(size_t)r0 * ldC + col] = hv;
                    *(__half2*)&outL[(size_t)r0 * ldC + col] = lv;
                }
                if (r0 + 8 < M) {
                    __half2 hv = __float22half2_rn(make_float2(v10, v11));
                    float2 hf = __half22float2(hv);
                    __half2 lv = __float22half2_rn(make_float2(v10 - hf.x, v11 - hf.y));
                    *(__half2*)&outH[(size_t)(r0 + 8) * ldC + col] = hv;
                    *(__half2*)&outL[(size_t)(r0 + 8) * ldC + col] = lv;
                }
            }
        }
    }
}

// ---------------- both edge scatters in one launch -----------------------------
__global__ void __launch_bounds__(256)
scatter2_kernel(const float* __restrict__ tmpi, const int* __restrict__ srci,
                const int* __restrict__ dsti, float* __restrict__ outu, int E2,
                const float* __restrict__ tmpu, const int* __restrict__ srcu,
                const int* __restrict__ dstu, float* __restrict__ outi, int E1)
{
    int idx = blockIdx.x * blockDim.x + threadIdx.x;
    int e = idx >> 5;
    const float* feat; const int* src; const int* dst; float* out;
    if (e < E2) { feat = tmpi; src = srci; dst = dsti; out = outu; }
    else {
        e -= E2;
        if (e >= E1) return;
        feat = tmpu; src = srcu; dst = dstu; out = outi;
    }
    int c = (idx & 31) * 4;
    int s = __ldg(&src[e]);
    int d = __ldg(&dst[e]);
    float4 v = *(const float4*)&feat[(size_t)s * FD + c];
    float* o = &out[(size_t)d * FD + c];
    asm volatile("red.global.add.v4.f32 [%0], {%1, %2, %3, %4};"
                 :: "l"(o), "f"(v.x), "f"(v.y), "f"(v.z), "f"(v.w) : "memory");
}

// ---------------- LN -> ReLU -> +residual (both types), emit fp16 hi/lo -------
__global__ void __launch_bounds__(256)
ln_all_kernel(const float* __restrict__ h,
              const float* __restrict__ fu, const float* __restrict__ fi,
              const float* __restrict__ gu, const float* __restrict__ bu,
              const float* __restrict__ gi, const float* __restrict__ bi,
              __half* __restrict__ outH, __half* __restrict__ outL,
              int Mu, int Mt)
{
    int row = blockIdx.x * 8 + threadIdx.y;
    if (row >= Mt) return;
    int lane = threadIdx.x;
    const bool isU = row < Mu;
    const float* feat = isU ? fu + (size_t)row * FD : fi + (size_t)(row - Mu) * FD;
    const float* g = isU ? gu : gi;
    const float* b = isU ? bu : bi;

    float4 x = *(const float4*)&h[(size_t)row * FD + lane * 4];
    float s = x.x + x.y + x.z + x.w;
    #pragma unroll
    for (int off = 16; off > 0; off >>= 1) s += __shfl_xor_sync(0xffffffffu, s, off);
    float mean = s * (1.0f / FD);
    float dx = x.x - mean, dy = x.y - mean, dz = x.z - mean, dw = x.w - mean;
    float q = dx * dx + dy * dy + dz * dz + dw * dw;
    #pragma unroll
    for (int off = 16; off > 0; off >>= 1) q += __shfl_xor_sync(0xffffffffu, q, off);
    float rstd = rsqrtf(q * (1.0f / FD) + 1e-5f);

    float4 gv = *(const float4*)&g[lane * 4];
    float4 bv = *(const float4*)&b[lane * 4];
    float4 fv = *(const float4*)&feat[lane * 4];
    float4 o;
    o.x = fmaxf(dx * rstd * gv.x + bv.x, 0.f) + fv.x;
    o.y = fmaxf(dy * rstd * gv.y + bv.y, 0.f) + fv.y;
    o.z = fmaxf(dz * rstd * gv.z + bv.z, 0.f) + fv.z;
    o.w = fmaxf(dw * rstd * gv.w + bv.w, 0.f) + fv.w;

    __half2 h01 = __float22half2_rn(make_float2(o.x, o.y));
    __half2 h23 = __float22half2_rn(make_float2(o.z, o.w));
    float2 f01 = __half22float2(h01);
    float2 f23 = __half22float2(h23);
    __half2 l01 = __float22half2_rn(make_float2(o.x - f01.x, o.y - f01.y));
    __half2 l23 = __float22half2_rn(make_float2(o.z - f23.x, o.w - f23.y));
    uint2 hv = make_uint2(*(uint32_t*)&h01, *(uint32_t*)&h23);
    uint2 lv = make_uint2(*(uint32_t*)&l01, *(uint32_t*)&l23);
    *(uint2*)&outH[(size_t)row * FD + lane * 4] = hv;
    *(uint2*)&outL[(size_t)row * FD + lane * 4] = lv;
}

// ---------------- launch ------------------------------------------------------
extern "C" void kernel_launch(void* const* d_in, const int* in_sizes, int n_in,
                              void* d_out, int out_size)
{
    const float* feat_user   = (const float*)d_in[0];
    const float* feat_item   = (const float*)d_in[1];
    const float* W_u2i       = (const float*)d_in[2];
    const float* b_u2i       = (const float*)d_in[3];
    const float* W_i2u       = (const float*)d_in[4];
    const float* b_i2u       = (const float*)d_in[5];
    const float* self_w_user = (const float*)d_in[6];
    const float* self_w_item = (const float*)d_in[7];
    const float* ln_g_user   = (const float*)d_in[8];
    const float* ln_b_user   = (const float*)d_in[9];
    const float* ln_g_item   = (const float*)d_in[10];
    const float* ln_b_item   = (const float*)d_in[11];
    const float* ffn_w1      = (const float*)d_in[12];
    const float* ffn_b1      = (const float*)d_in[13];
    const float* ffn_w2      = (const float*)d_in[14];
    const float* ffn_b2      = (const float*)d_in[15];
    const int*   src_u2i     = (const int*)d_in[16];
    const int*   dst_u2i     = (const int*)d_in[17];
    const int*   src_i2u     = (const int*)d_in[18];
    const int*   dst_i2u     = (const int*)d_in[19];

    const int Mu = in_sizes[0] / FD;
    const int Mi = in_sizes[1] / FD;
    const int E1 = in_sizes[16];
    const int E2 = in_sizes[18];
    float* out = (float*)d_out;

    auto sym = [](const void* s) { void* p; cudaGetSymbolAddress(&p, s); return p; };
    float* tmp_u = (float*)sym(g_tmp_u);
    float* tmp_i = (float*)sym(g_tmp_i);
    float* h     = (float*)sym(g_h);
    __half* fu_h = (__half*)sym(g_fu_h);
    __half* fu_l = (__half*)sym(g_fu_l);
    __half* fi_h = (__half*)sym(g_fi_h);
    __half* fi_l = (__half*)sym(g_fi_l);
    __half* hh   = (__half*)sym(g_hh);
    __half* hl   = (__half*)sym(g_hl);
    __half* zh   = (__half*)sym(g_zh);
    __half* zl   = (__half*)sym(g_zl);
    __half* w_u2i = (__half*)sym(g_w_u2i);
    __half* w_i2u = (__half*)sym(g_w_i2u);
    __half* w_su  = (__half*)sym(g_w_su);
    __half* w_si  = (__half*)sym(g_w_si);
    __half* w_f1  = (__half*)sym(g_w_f1);
    __half* w_f2  = (__half*)sym(g_w_f2);

    float* h_user = h;
    float* h_item = h + (size_t)Mu * FD;

    const int SMEM = 98304;
    cudaFuncSetAttribute(gemm_mma, cudaFuncAttributeMaxDynamicSharedMemorySize, SMEM);

    // 0: all weight transposes (1 launch) + both feature splits (1 launch)
    wtrans_all<<<dim3(128, 6), 256>>>(W_u2i, W_i2u, self_w_user, self_w_item,
                                      ffn_w1, ffn_w2,
                                      w_u2i, w_i2u, w_su, w_si, w_f1, w_f2);
    {
        int n4u = Mu * FD / 4, n4i = Mi * FD / 4;
        int gx = (max(n4u, n4i) + 255) / 256;
        split_feat<<<dim3(gx, 2), 256>>>(feat_user, feat_item,
                                         fu_h, fu_l, fi_h, fi_l, n4u, n4i);
    }

    // 1: user feats x {W_u2i -> tmp_u | self_w_user + b_i2u -> h_user}
    gemm_mma<<<dim3((Mu + 127) / 128, 2), 256, SMEM>>>(
        fu_h, fu_l, w_u2i, w_su, nullptr, b_i2u,
        tmp_u, h_user, nullptr, nullptr, Mu, FD, FD, 0, 0);
    // 2: item feats x {W_i2u -> tmp_i | self_w_item + b_u2i -> h_item}
    gemm_mma<<<dim3((Mi + 127) / 128, 2), 256, SMEM>>>(
        fi_h, fi_l, w_i2u, w_si, nullptr, b_u2i,
        tmp_i, h_item, nullptr, nullptr, Mi, FD, FD, 0, 0);

    // 3: both edge scatters (1 launch)
    {
        long long tot = (long long)(E1 + E2) * 32;
        scatter2_kernel<<<(int)((tot + 255) / 256), 256>>>(
            tmp_i, src_i2u, dst_i2u, h_user, E2,
            tmp_u, src_u2i, dst_u2i, h_item, E1);
    }

    // 4: LN -> ReLU -> residual for both types (1 launch), emit fp16 hi/lo
    const int Mt = Mu + Mi;
    {
        dim3 lblk(32, 8);
        ln_all_kernel<<<(Mt + 7) / 8, lblk>>>(h, feat_user, feat_item,
                                              ln_g_user, ln_b_user, ln_g_item, ln_b_item,
                                              hh, hl, Mu, Mt);
    }

    // 5: FFN1: [Mt,128] @ w1 -> relu -> fp16 split z (N=256 via grid.y halves)
    gemm_mma<<<dim3((Mt + 127) / 128, 2), 256, SMEM>>>(
        hh, hl, w_f1, w_f1 + 128 * FD, ffn_b1, ffn_b1,
        nullptr, nullptr, zh, zl, Mt, FD, FH, 128, 1);
    // 6: FFN2: [Mt,256] @ w2 + b2 -> out (f32)
    gemm_mma<<<dim3((Mt + 127) / 128, 1), 256, SMEM>>>(
        zh, zl, w_f2, w_f2, ffn_b2, ffn_b2,
        out, out, nullptr, nullptr, Mt, FH, FD, 0, 0);
}